// round 15
// baseline (speedup 1.0000x reference)
#include <cuda_runtime.h>
#include <cuda_fp16.h>
#include <math.h>
#include <stdint.h>

#define N_NODES 100000
#define N_NNZ   1000000
#define F_IN    1433
#define F_HID   128
#define F_OUT   64
#define N_POS   20000
#define N_EDGES 40000
#define INV_N   (1.0f / (float)N_NODES)

#define SCAN_BS 1024
#define SCAN_NB ((N_NODES + 1 + SCAN_BS - 1) / SCAN_BS)   // 98

// ---------------- scratch (static device globals; no allocation) -------------
__device__ __half g_support[(size_t)N_NODES * F_HID];
__device__ float  g_x[(size_t)N_NODES * F_HID];
__device__ float  g_colsum[3][F_HID];
__device__ float  g_inv[N_NODES];
__device__ int    g_row_ptr[N_NODES + 1];
__device__ int    g_row_work[N_NODES + 1];
__device__ int    g_csr_col[N_NNZ];
__device__ float  g_csr_val[N_NNZ];
__device__ int    g_blocksum[SCAN_NB];

// ================= helpers ===================================================
__device__ __forceinline__ uint32_t smem_u32(const void* p) {
    uint32_t a;
    asm("{ .reg .u64 t; cvta.to.shared.u64 t, %1; cvt.u32.u64 %0, t; }"
        : "=r"(a) : "l"(p));
    return a;
}

__device__ __forceinline__ uint32_t pack_f16x2(float f_up, float f_lo) {
    uint32_t r;
    asm("cvt.rn.f16x2.f32 %0, %1, %2;" : "=r"(r) : "f"(f_up), "f"(f_lo));
    return r;
}

#define MMA_F16(d, A0, A1, A2, A3, B0, B1)                                      \
    asm volatile(                                                               \
        "mma.sync.aligned.m16n8k16.row.col.f32.f16.f16.f32 "                    \
        "{%0,%1,%2,%3}, {%4,%5,%6,%7}, {%8,%9}, {%0,%1,%2,%3};"                 \
        : "+f"((d)[0]), "+f"((d)[1]), "+f"((d)[2]), "+f"((d)[3])                \
        : "r"(A0), "r"(A1), "r"(A2), "r"(A3), "r"(B0), "r"(B1));

#define LDMATRIX_X4(r0, r1, r2, r3, addr)                                       \
    asm volatile(                                                               \
        "ldmatrix.sync.aligned.m8n8.x4.shared.b16 {%0,%1,%2,%3}, [%4];"         \
        : "=r"(r0), "=r"(r1), "=r"(r2), "=r"(r3) : "r"(addr));

// ================= fp16 1-term tensor-core GEMM ==============================
// C[Nrows, NC] (fp16) = normA[Nrows, K] @ W[K, NC].
// DONORM: A'[r,k] = (A[r,k] - msrc[k]/N) * inv[r]  (PairNorm folded in).
#define A_STRIDE 80

template <int NC, bool DONORM>
__global__ __launch_bounds__(256)
void f16_gemm_kernel(const float* __restrict__ A, const float* __restrict__ B,
                     __half* __restrict__ C, int Nrows, int K,
                     const float* __restrict__ msrc,
                     const float* __restrict__ inv) {
    constexpr int NI = NC / 16;
    constexpr int SB = NC + 8;
    constexpr int BITERS = (16 * (NC / 4)) / 256;

    __shared__ __align__(16) uint8_t As[128 * A_STRIDE];
    __shared__ uint32_t Bs[16][SB];

    const int tid  = threadIdx.x;
    const int wid  = tid >> 5;
    const int lane = tid & 31;
    const int g    = lane >> 2;
    const int tg   = lane & 3;
    const int wr   = (wid & 3) * 32;
    const int wc   = (wid >> 2) * (NC / 2);
    const int rowBase = blockIdx.x * 128;

    const uint32_t asBase = smem_u32(As);

    float acc[2][NI][4];
#pragma unroll
    for (int mi = 0; mi < 2; mi++)
#pragma unroll
        for (int ni = 0; ni < NI; ni++)
#pragma unroll
            for (int r = 0; r < 4; r++) acc[mi][ni][r] = 0.0f;

    const int aRow0 = wid * 16;
    float fa[16];

    auto load_A = [&](int kt) {
        const int kglob = kt * 32 + lane;
        const bool kOK = kglob < K;
#pragma unroll
        for (int i = 0; i < 16; i++) {
            const int gr = rowBase + aRow0 + i;
            fa[i] = (kOK && gr < Nrows) ? A[(size_t)gr * K + kglob] : 0.0f;
        }
    };

    auto store_A = [&](int kt) {
        float mk = 0.0f;
        if (DONORM) {
            const int kglob = kt * 32 + lane;
            mk = (kglob < K) ? msrc[kglob] * INV_N : 0.0f;
        }
#pragma unroll
        for (int i = 0; i < 16; i++) {
            float v = fa[i];
            if (DONORM) {
                const int gr = rowBase + aRow0 + i;
                const float ir = (gr < Nrows) ? inv[gr] : 0.0f;
                const int kglob = kt * 32 + lane;
                v = (kglob < K && gr < Nrows) ? (v - mk) * ir : 0.0f;
            }
            const uint32_t addr = asBase + (aRow0 + i) * A_STRIDE + lane * 2;
            const __half h = __float2half_rn(v);
            const unsigned short hu = *reinterpret_cast<const unsigned short*>(&h);
            asm volatile("st.shared.b16 [%0], %1;" :: "r"(addr), "h"(hu) : "memory");
        }
    };

    const int lmRow = lane & 15;
    const int lmKoff = (lane >> 4) * 16;

    const int KT = (K + 31) / 32;
    load_A(0);

    for (int kt = 0; kt < KT; kt++) {
        store_A(kt);

#pragma unroll
        for (int it = 0; it < BITERS; it++) {
            const int slot = tid + it * 256;
            const int kp = slot / (NC / 4);
            const int n4 = slot % (NC / 4);
            const int kg0 = kt * 32 + 2 * kp;
            float4 v0 = make_float4(0.f, 0.f, 0.f, 0.f);
            float4 v1 = make_float4(0.f, 0.f, 0.f, 0.f);
            if (kg0 < K)
                v0 = *reinterpret_cast<const float4*>(B + (size_t)kg0 * NC + n4 * 4);
            if (kg0 + 1 < K)
                v1 = *reinterpret_cast<const float4*>(B + (size_t)(kg0 + 1) * NC + n4 * 4);
            Bs[kp][n4 * 4 + 0] = pack_f16x2(v1.x, v0.x);
            Bs[kp][n4 * 4 + 1] = pack_f16x2(v1.y, v0.y);
            Bs[kp][n4 * 4 + 2] = pack_f16x2(v1.z, v0.z);
            Bs[kp][n4 * 4 + 3] = pack_f16x2(v1.w, v0.w);
        }
        __syncthreads();

        if (kt + 1 < KT) load_A(kt + 1);

#pragma unroll
        for (int ks = 0; ks < 2; ks++) {
            uint32_t a[2][4];
#pragma unroll
            for (int mi = 0; mi < 2; mi++) {
                const uint32_t addr = asBase +
                    (wr + mi * 16 + lmRow) * A_STRIDE + ks * 32 + lmKoff;
                LDMATRIX_X4(a[mi][0], a[mi][1], a[mi][2], a[mi][3], addr);
            }
#pragma unroll
            for (int ni = 0; ni < NI; ni++) {
                const int col = wc + ni * 8 + g;
                const uint32_t b0 = Bs[ks * 8 + tg][col];
                const uint32_t b1 = Bs[ks * 8 + tg + 4][col];
#pragma unroll
                for (int mi = 0; mi < 2; mi++) {
                    MMA_F16(acc[mi][ni], a[mi][0], a[mi][1], a[mi][2], a[mi][3],
                            b0, b1);
                }
            }
        }
        __syncthreads();
    }

    // ---- store C as packed fp16 pairs ----
#pragma unroll
    for (int mi = 0; mi < 2; mi++) {
#pragma unroll
        for (int ni = 0; ni < NI; ni++) {
            const int col = wc + ni * 8 + tg * 2;
            const int r0  = rowBase + wr + mi * 16 + g;
            if (r0 < Nrows) {
                uint32_t pk = pack_f16x2(acc[mi][ni][1], acc[mi][ni][0]);
                *reinterpret_cast<uint32_t*>(C + (size_t)r0 * NC + col) = pk;
            }
            if (r0 + 8 < Nrows) {
                uint32_t pk = pack_f16x2(acc[mi][ni][3], acc[mi][ni][2]);
                *reinterpret_cast<uint32_t*>(C + (size_t)(r0 + 8) * NC + col) = pk;
            }
        }
    }
}

// ================= CSR build ==================================================
__global__ void hist_zero_kernel(int* __restrict__ row_ptr, float* __restrict__ colsum) {
    int i = blockIdx.x * blockDim.x + threadIdx.x;
    if (i <= N_NODES) row_ptr[i] = 0;
    if (i < 3 * F_HID) colsum[i] = 0.0f;
}

__global__ void hist_kernel(const int* __restrict__ row, int* __restrict__ row_ptr) {
    int i = blockIdx.x * blockDim.x + threadIdx.x;
    if (i < N_NNZ) atomicAdd(&row_ptr[row[i] + 1], 1);
}

__global__ __launch_bounds__(SCAN_BS)
void scan_a_kernel(int* __restrict__ data, int* __restrict__ blocksum, int n) {
    __shared__ int sh[SCAN_BS];
    int gid = blockIdx.x * SCAN_BS + threadIdx.x;
    int v = (gid < n) ? data[gid] : 0;
    sh[threadIdx.x] = v;
    __syncthreads();
#pragma unroll
    for (int o = 1; o < SCAN_BS; o <<= 1) {
        int t = (threadIdx.x >= o) ? sh[threadIdx.x - o] : 0;
        __syncthreads();
        sh[threadIdx.x] += t;
        __syncthreads();
    }
    if (gid < n) data[gid] = sh[threadIdx.x];
    if (threadIdx.x == SCAN_BS - 1) blocksum[blockIdx.x] = sh[threadIdx.x];
}

__global__ __launch_bounds__(SCAN_BS)
void scan_b_kernel(int* __restrict__ blocksum, int nb) {
    __shared__ int sh[SCAN_BS];
    int v = (threadIdx.x < nb) ? blocksum[threadIdx.x] : 0;
    sh[threadIdx.x] = v;
    __syncthreads();
#pragma unroll
    for (int o = 1; o < SCAN_BS; o <<= 1) {
        int t = (threadIdx.x >= o) ? sh[threadIdx.x - o] : 0;
        __syncthreads();
        sh[threadIdx.x] += t;
        __syncthreads();
    }
    if (threadIdx.x < nb) blocksum[threadIdx.x] = sh[threadIdx.x];
}

__global__ __launch_bounds__(SCAN_BS)
void scan_c_kernel(int* __restrict__ data, const int* __restrict__ blocksum,
                   int* __restrict__ work, int n) {
    int gid = blockIdx.x * SCAN_BS + threadIdx.x;
    if (gid >= n) return;
    int v = data[gid];
    if (blockIdx.x > 0) v += blocksum[blockIdx.x - 1];
    data[gid] = v;
    work[gid] = v;
}

__global__ void scatter_kernel(const int* __restrict__ row, const int* __restrict__ col,
                               const float* __restrict__ val,
                               int* __restrict__ work,
                               int* __restrict__ csr_col, float* __restrict__ csr_val) {
    int i = blockIdx.x * blockDim.x + threadIdx.x;
    if (i >= N_NNZ) return;
    int pos = atomicAdd(&work[row[i]], 1);
    csr_col[pos] = col[i];
    csr_val[pos] = val[i];
}

// ================= fused CSR aggregation (fp16 gather) =======================
template <int F, int VPL>
__global__ __launch_bounds__(256)
void csr_agg_kernel(const int* __restrict__ row_ptr,
                    const int* __restrict__ csr_col,
                    const float* __restrict__ csr_val,
                    const __half* __restrict__ X,
                    const float* __restrict__ bias,
                    float* __restrict__ Xout,
                    float* __restrict__ colsum) {
    __shared__ float scol[F];
    const int tid  = threadIdx.x;
    const int wid  = tid >> 5;
    const int lane = tid & 31;

    if (tid < F) scol[tid] = 0.0f;
    __syncthreads();

    float bz[VPL];
#pragma unroll
    for (int j = 0; j < VPL; j++) bz[j] = bias[lane * VPL + j];

    float csum[VPL];
#pragma unroll
    for (int j = 0; j < VPL; j++) csum[j] = 0.0f;

    const int rowBase = blockIdx.x * 32 + wid * 4;

#pragma unroll
    for (int rr = 0; rr < 4; rr++) {
        const int r = rowBase + rr;
        const int start = row_ptr[r];
        const int end   = row_ptr[r + 1];

        float acc[VPL];
#pragma unroll
        for (int j = 0; j < VPL; j++) acc[j] = 0.0f;

        for (int base = start; base < end; base += 32) {
            int idx = base + lane;
            int   cv = 0;
            float vv = 0.0f;
            if (idx < end) { cv = csr_col[idx]; vv = csr_val[idx]; }
            int count = min(32, end - base);
            for (int j = 0; j < count; j++) {
                int   c = __shfl_sync(0xffffffffu, cv, j);
                float v = __shfl_sync(0xffffffffu, vv, j);
                if (VPL == 4) {
                    const uint2* xr = reinterpret_cast<const uint2*>(X + (size_t)c * F);
                    uint2 u = xr[lane];
                    float2 f0 = __half22float2(*reinterpret_cast<__half2*>(&u.x));
                    float2 f1 = __half22float2(*reinterpret_cast<__half2*>(&u.y));
                    acc[0] = fmaf(v, f0.x, acc[0]);
                    acc[1] = fmaf(v, f0.y, acc[1]);
                    acc[2] = fmaf(v, f1.x, acc[2]);
                    acc[3] = fmaf(v, f1.y, acc[3]);
                } else {
                    const uint32_t* xr = reinterpret_cast<const uint32_t*>(X + (size_t)c * F);
                    uint32_t u = xr[lane];
                    float2 f0 = __half22float2(*reinterpret_cast<__half2*>(&u));
                    acc[0] = fmaf(v, f0.x, acc[0]);
                    acc[1] = fmaf(v, f0.y, acc[1]);
                }
            }
        }

#pragma unroll
        for (int j = 0; j < VPL; j++) {
            float o = fmaxf(acc[j] + bz[j], 0.0f);
            acc[j] = o;
            csum[j] += o;
        }
        float* od = Xout + (size_t)r * F;
        if (VPL == 4) {
            reinterpret_cast<float4*>(od)[lane] =
                make_float4(acc[0], acc[1], acc[2], acc[3]);
        } else {
            reinterpret_cast<float2*>(od)[lane] = make_float2(acc[0], acc[1]);
        }
    }

#pragma unroll
    for (int j = 0; j < VPL; j++)
        atomicAdd(&scol[lane * VPL + j], csum[j]);
    __syncthreads();
    if (tid < F) atomicAdd(&colsum[tid], scol[tid]);
}

// ================= row stats: inv[r] = rsqrt(eps + ||x_r - m||^2) ============
// F = 128 only (layers 0,1). Warp per row; lane covers float4.
__global__ __launch_bounds__(256)
void rowstat_kernel(const float* __restrict__ X, const float* __restrict__ colsum,
                    float* __restrict__ inv, int N) {
    const int warp = (blockIdx.x * blockDim.x + threadIdx.x) >> 5;
    const int lane = threadIdx.x & 31;
    if (warp >= N) return;
    const float4 x4 = reinterpret_cast<const float4*>(X + (size_t)warp * F_HID)[lane];
    const float4 c4 = reinterpret_cast<const float4*>(colsum)[lane];
    const float d0 = x4.x - c4.x * INV_N;
    const float d1 = x4.y - c4.y * INV_N;
    const float d2 = x4.z - c4.z * INV_N;
    const float d3 = x4.w - c4.w * INV_N;
    float s = d0 * d0 + d1 * d1 + d2 * d2 + d3 * d3;
#pragma unroll
    for (int o = 16; o > 0; o >>= 1)
        s += __shfl_xor_sync(0xffffffffu, s, o);
    if (lane == 0) inv[warp] = rsqrtf(1e-6f + s);
}

// ---------------- decode with fused final PairNorm ---------------------------
// logits = <xa-m, xb-m> / (sqrt(eps+||xa-m||^2) * sqrt(eps+||xb-m||^2))
__global__ __launch_bounds__(128)
void decode_kernel(const float* __restrict__ X, const float* __restrict__ colsum,
                   const int* __restrict__ pos, const int* __restrict__ neg,
                   float* __restrict__ out) {
    int warp = (blockIdx.x * blockDim.x + threadIdx.x) >> 5;
    int lane = threadIdx.x & 31;
    if (warp >= N_EDGES) return;
    const int* e = (warp < N_POS) ? (pos + 2 * warp) : (neg + 2 * (warp - N_POS));
    int an = e[0];
    int bn = e[1];
    const float* xa = X + (size_t)an * F_OUT;
    const float* xb = X + (size_t)bn * F_OUT;
    const float m0 = colsum[lane] * INV_N;
    const float m1 = colsum[lane + 32] * INV_N;
    const float a0 = xa[lane] - m0, a1 = xa[lane + 32] - m1;
    const float b0 = xb[lane] - m0, b1 = xb[lane + 32] - m1;
    float saa = a0 * a0 + a1 * a1;
    float sbb = b0 * b0 + b1 * b1;
    float sab = a0 * b0 + a1 * b1;
#pragma unroll
    for (int o = 16; o > 0; o >>= 1) {
        saa += __shfl_xor_sync(0xffffffffu, saa, o);
        sbb += __shfl_xor_sync(0xffffffffu, sbb, o);
        sab += __shfl_xor_sync(0xffffffffu, sab, o);
    }
    if (lane == 0) {
        float s = sab * rsqrtf(1e-6f + saa) * rsqrtf(1e-6f + sbb);
        out[warp] = 1.0f / (1.0f + expf(-s));
    }
}

// ---------------- host orchestration -----------------------------------------
extern "C" void kernel_launch(void* const* d_in, const int* in_sizes, int n_in,
                              void* d_out, int out_size) {
    const float* in_feature = (const float*)d_in[0];
    const int*   adj_row    = (const int*)d_in[1];
    const int*   adj_col    = (const int*)d_in[2];
    const float* adj_val    = (const float*)d_in[3];
    const int*   pos_edge   = (const int*)d_in[4];
    const int*   neg_edge   = (const int*)d_in[5];
    const float* W0 = (const float*)d_in[6];
    const float* b0 = (const float*)d_in[7];
    const float* W1 = (const float*)d_in[8];
    const float* b1 = (const float*)d_in[9];
    const float* W2 = (const float*)d_in[10];
    const float* b2 = (const float*)d_in[11];
    float* out = (float*)d_out;

    __half* support;
    float *x, *colsum, *csr_val, *inv;
    int *row_ptr, *row_work, *csr_col, *blocksum;
    cudaGetSymbolAddress((void**)&support,  g_support);
    cudaGetSymbolAddress((void**)&x,        g_x);
    cudaGetSymbolAddress((void**)&colsum,   g_colsum);
    cudaGetSymbolAddress((void**)&inv,      g_inv);
    cudaGetSymbolAddress((void**)&row_ptr,  g_row_ptr);
    cudaGetSymbolAddress((void**)&row_work, g_row_work);
    cudaGetSymbolAddress((void**)&csr_col,  g_csr_col);
    cudaGetSymbolAddress((void**)&csr_val,  g_csr_val);
    cudaGetSymbolAddress((void**)&blocksum, g_blocksum);

    const int gBlocks   = (N_NODES + 127) / 128;
    const int aggBlocks = N_NODES / 32;             // 3125
    const int rsBlocks  = (N_NODES * 32 + 255) / 256;

    // ---- build CSR (once; reused by all 3 layers); also zero colsums ----
    hist_zero_kernel<<<(N_NODES + 1 + 255) / 256, 256>>>(row_ptr, colsum);
    hist_kernel<<<(N_NNZ + 255) / 256, 256>>>(adj_row, row_ptr);
    scan_a_kernel<<<SCAN_NB, SCAN_BS>>>(row_ptr, blocksum, N_NODES + 1);
    scan_b_kernel<<<1, SCAN_BS>>>(blocksum, SCAN_NB);
    scan_c_kernel<<<SCAN_NB, SCAN_BS>>>(row_ptr, blocksum, row_work, N_NODES + 1);
    scatter_kernel<<<(N_NNZ + 255) / 256, 256>>>(adj_row, adj_col, adj_val,
                                                 row_work, csr_col, csr_val);

    // ---- layer 0 (raw input, no norm) ----
    f16_gemm_kernel<128, false><<<gBlocks, 256>>>(in_feature, W0, support,
                                                  N_NODES, F_IN, nullptr, nullptr);
    csr_agg_kernel<128, 4><<<aggBlocks, 256>>>(row_ptr, csr_col, csr_val,
                                               support, b0, x, colsum + 0 * F_HID);
    rowstat_kernel<<<rsBlocks, 256>>>(x, colsum + 0 * F_HID, inv, N_NODES);

    // ---- layer 1 (norm folded into GEMM A-path) ----
    f16_gemm_kernel<128, true><<<gBlocks, 256>>>(x, W1, support, N_NODES, F_HID,
                                                 colsum + 0 * F_HID, inv);
    csr_agg_kernel<128, 4><<<aggBlocks, 256>>>(row_ptr, csr_col, csr_val,
                                               support, b1, x, colsum + 1 * F_HID);
    rowstat_kernel<<<rsBlocks, 256>>>(x, colsum + 1 * F_HID, inv, N_NODES);

    // ---- layer 2 ----
    f16_gemm_kernel<64, true><<<gBlocks, 256>>>(x, W2, support, N_NODES, F_HID,
                                                colsum + 1 * F_HID, inv);
    csr_agg_kernel<64, 2><<<aggBlocks, 256>>>(row_ptr, csr_col, csr_val,
                                              support, b2, x, colsum + 2 * F_HID);

    // ---- decode with fused final pairnorm ----
    decode_kernel<<<(N_EDGES * 32 + 127) / 128, 128>>>(x, colsum + 2 * F_HID,
                                                       pos_edge, neg_edge, out);
}

// round 17
// speedup vs baseline: 1.1537x; 1.1537x over previous
#include <cuda_runtime.h>
#include <cuda_fp16.h>
#include <math.h>
#include <stdint.h>

#define N_NODES 100000
#define N_NNZ   1000000
#define F_IN    1433
#define F_HID   128
#define F_OUT   64
#define N_POS   20000
#define N_EDGES 40000
#define INV_N   (1.0f / (float)N_NODES)

#define SCAN_BS 1024
#define SCAN_NB ((N_NODES + 1 + SCAN_BS - 1) / SCAN_BS)   // 98

// ---------------- scratch (static device globals; no allocation) -------------
__device__ __half g_support[(size_t)N_NODES * F_HID];
__device__ float  g_x[(size_t)N_NODES * F_HID];
__device__ float  g_colsum[3][F_HID];
__device__ int    g_row_ptr[N_NODES + 1];
__device__ int    g_row_work[N_NODES + 1];
__device__ int    g_csr_col[N_NNZ];
__device__ float  g_csr_val[N_NNZ];
__device__ int    g_blocksum[SCAN_NB];

// ================= helpers ===================================================
__device__ __forceinline__ uint32_t smem_u32(const void* p) {
    uint32_t a;
    asm("{ .reg .u64 t; cvta.to.shared.u64 t, %1; cvt.u32.u64 %0, t; }"
        : "=r"(a) : "l"(p));
    return a;
}

__device__ __forceinline__ uint32_t pack_f16x2(float f_up, float f_lo) {
    uint32_t r;
    asm("cvt.rn.f16x2.f32 %0, %1, %2;" : "=r"(r) : "f"(f_up), "f"(f_lo));
    return r;
}

#define MMA_F16(d, A0, A1, A2, A3, B0, B1)                                      \
    asm volatile(                                                               \
        "mma.sync.aligned.m16n8k16.row.col.f32.f16.f16.f32 "                    \
        "{%0,%1,%2,%3}, {%4,%5,%6,%7}, {%8,%9}, {%0,%1,%2,%3};"                 \
        : "+f"((d)[0]), "+f"((d)[1]), "+f"((d)[2]), "+f"((d)[3])                \
        : "r"(A0), "r"(A1), "r"(A2), "r"(A3), "r"(B0), "r"(B1));

#define LDMATRIX_X4(r0, r1, r2, r3, addr)                                       \
    asm volatile(                                                               \
        "ldmatrix.sync.aligned.m8n8.x4.shared.b16 {%0,%1,%2,%3}, [%4];"         \
        : "=r"(r0), "=r"(r1), "=r"(r2), "=r"(r3) : "r"(addr));

// ================= fp16 GEMM for K=1433 (layer 0) ============================
#define A_STRIDE 80

__global__ __launch_bounds__(256)
void f16_gemm_kernel(const float* __restrict__ A, const float* __restrict__ B,
                     __half* __restrict__ C, int Nrows, int K) {
    constexpr int NC = 128;
    constexpr int NI = NC / 16;
    constexpr int SB = NC + 8;
    constexpr int BITERS = (16 * (NC / 4)) / 256;

    __shared__ __align__(16) uint8_t As[128 * A_STRIDE];
    __shared__ uint32_t Bs[16][SB];

    const int tid  = threadIdx.x;
    const int wid  = tid >> 5;
    const int lane = tid & 31;
    const int g    = lane >> 2;
    const int tg   = lane & 3;
    const int wr   = (wid & 3) * 32;
    const int wc   = (wid >> 2) * (NC / 2);
    const int rowBase = blockIdx.x * 128;

    const uint32_t asBase = smem_u32(As);

    float acc[2][NI][4];
#pragma unroll
    for (int mi = 0; mi < 2; mi++)
#pragma unroll
        for (int ni = 0; ni < NI; ni++)
#pragma unroll
            for (int r = 0; r < 4; r++) acc[mi][ni][r] = 0.0f;

    const int aRow0 = wid * 16;
    float fa[16];

    auto load_A = [&](int kt) {
        const int kglob = kt * 32 + lane;
        const bool kOK = kglob < K;
#pragma unroll
        for (int i = 0; i < 16; i++) {
            const int gr = rowBase + aRow0 + i;
            fa[i] = (kOK && gr < Nrows) ? A[(size_t)gr * K + kglob] : 0.0f;
        }
    };

    auto store_A = [&]() {
#pragma unroll
        for (int i = 0; i < 16; i++) {
            const uint32_t addr = asBase + (aRow0 + i) * A_STRIDE + lane * 2;
            const __half h = __float2half_rn(fa[i]);
            const unsigned short hu = *reinterpret_cast<const unsigned short*>(&h);
            asm volatile("st.shared.b16 [%0], %1;" :: "r"(addr), "h"(hu) : "memory");
        }
    };

    const int lmRow = lane & 15;
    const int lmKoff = (lane >> 4) * 16;

    const int KT = (K + 31) / 32;
    load_A(0);

    for (int kt = 0; kt < KT; kt++) {
        store_A();

#pragma unroll
        for (int it = 0; it < BITERS; it++) {
            const int slot = tid + it * 256;
            const int kp = slot / (NC / 4);
            const int n4 = slot % (NC / 4);
            const int kg0 = kt * 32 + 2 * kp;
            float4 v0 = make_float4(0.f, 0.f, 0.f, 0.f);
            float4 v1 = make_float4(0.f, 0.f, 0.f, 0.f);
            if (kg0 < K)
                v0 = *reinterpret_cast<const float4*>(B + (size_t)kg0 * NC + n4 * 4);
            if (kg0 + 1 < K)
                v1 = *reinterpret_cast<const float4*>(B + (size_t)(kg0 + 1) * NC + n4 * 4);
            Bs[kp][n4 * 4 + 0] = pack_f16x2(v1.x, v0.x);
            Bs[kp][n4 * 4 + 1] = pack_f16x2(v1.y, v0.y);
            Bs[kp][n4 * 4 + 2] = pack_f16x2(v1.z, v0.z);
            Bs[kp][n4 * 4 + 3] = pack_f16x2(v1.w, v0.w);
        }
        __syncthreads();

        if (kt + 1 < KT) load_A(kt + 1);

#pragma unroll
        for (int ks = 0; ks < 2; ks++) {
            uint32_t a[2][4];
#pragma unroll
            for (int mi = 0; mi < 2; mi++) {
                const uint32_t addr = asBase +
                    (wr + mi * 16 + lmRow) * A_STRIDE + ks * 32 + lmKoff;
                LDMATRIX_X4(a[mi][0], a[mi][1], a[mi][2], a[mi][3], addr);
            }
#pragma unroll
            for (int ni = 0; ni < NI; ni++) {
                const int col = wc + ni * 8 + g;
                const uint32_t b0 = Bs[ks * 8 + tg][col];
                const uint32_t b1 = Bs[ks * 8 + tg + 4][col];
#pragma unroll
                for (int mi = 0; mi < 2; mi++) {
                    MMA_F16(acc[mi][ni], a[mi][0], a[mi][1], a[mi][2], a[mi][3],
                            b0, b1);
                }
            }
        }
        __syncthreads();
    }

#pragma unroll
    for (int mi = 0; mi < 2; mi++) {
#pragma unroll
        for (int ni = 0; ni < NI; ni++) {
            const int col = wc + ni * 8 + tg * 2;
            const int r0  = rowBase + wr + mi * 16 + g;
            if (r0 < Nrows) {
                uint32_t pk = pack_f16x2(acc[mi][ni][1], acc[mi][ni][0]);
                *reinterpret_cast<uint32_t*>(C + (size_t)r0 * NC + col) = pk;
            }
            if (r0 + 8 < Nrows) {
                uint32_t pk = pack_f16x2(acc[mi][ni][3], acc[mi][ni][2]);
                *reinterpret_cast<uint32_t*>(C + (size_t)(r0 + 8) * NC + col) = pk;
            }
        }
    }
}

// ================= K=128 GEMM with in-kernel PairNorm (layers 1,2) ===========
// C[Nrows, NC] (fp16) = pairnorm(A)[Nrows, 128] @ W[128, NC].
// Loads each x-row once, computes inv_r = rsqrt(eps+||x-m||^2) via warp
// reduction, normalizes, converts fp16, runs all 8 k-steps from smem.
#define AS128 272   // bytes per A row: 128 halves (256B) + 16B pad; 16B-aligned

template <int NC>
__global__ __launch_bounds__(256)
void f16_gemm128_kernel(const float* __restrict__ A, const float* __restrict__ B,
                        __half* __restrict__ C, int Nrows,
                        const float* __restrict__ colsum) {
    constexpr int NI = NC / 16;
    constexpr int SB = NC + 8;
    constexpr int BSLOTS = 64 * (NC / 4);

    extern __shared__ __align__(16) uint8_t dyn[];
    uint8_t* As = dyn;                                       // 128 * 272
    uint32_t (*Bs)[SB] = reinterpret_cast<uint32_t(*)[SB]>(dyn + 128 * AS128);

    const int tid  = threadIdx.x;
    const int wid  = tid >> 5;
    const int lane = tid & 31;
    const int g    = lane >> 2;
    const int tg   = lane & 3;
    const int wr   = (wid & 3) * 32;
    const int wc   = (wid >> 2) * (NC / 2);
    const int rowBase = blockIdx.x * 128;

    const uint32_t asBase = smem_u32(As);

    // ---- A: load, normalize (PairNorm), fp16 -> smem ----
    const float4 c4 = reinterpret_cast<const float4*>(colsum)[lane];
    const float m0 = c4.x * INV_N, m1 = c4.y * INV_N;
    const float m2 = c4.z * INV_N, m3 = c4.w * INV_N;
    const int aRow0 = wid * 16;

#pragma unroll
    for (int i = 0; i < 16; i++) {
        const int gr = rowBase + aRow0 + i;
        float4 x4 = make_float4(0.f, 0.f, 0.f, 0.f);
        if (gr < Nrows)
            x4 = reinterpret_cast<const float4*>(A + (size_t)gr * 128)[lane];
        const float d0 = x4.x - m0, d1 = x4.y - m1;
        const float d2 = x4.z - m2, d3 = x4.w - m3;
        float s = d0 * d0 + d1 * d1 + d2 * d2 + d3 * d3;
#pragma unroll
        for (int o = 16; o > 0; o >>= 1)
            s += __shfl_xor_sync(0xffffffffu, s, o);
        const float ir = rsqrtf(1e-6f + s);
        const uint32_t p0 = pack_f16x2(d1 * ir, d0 * ir);
        const uint32_t p1 = pack_f16x2(d3 * ir, d2 * ir);
        const uint32_t addr = asBase + (aRow0 + i) * AS128 + lane * 8;
        asm volatile("st.shared.v2.b32 [%0], {%1,%2};"
                     :: "r"(addr), "r"(p0), "r"(p1) : "memory");
    }

    // ---- B: W[128][NC] -> Bs[kp][n] packed k-pairs ----
#pragma unroll
    for (int it = 0; it < BSLOTS / 256; it++) {
        const int slot = tid + it * 256;
        const int kp = slot / (NC / 4);
        const int n4 = slot % (NC / 4);
        const float4 v0 = *reinterpret_cast<const float4*>(B + (size_t)(2 * kp) * NC + n4 * 4);
        const float4 v1 = *reinterpret_cast<const float4*>(B + (size_t)(2 * kp + 1) * NC + n4 * 4);
        Bs[kp][n4 * 4 + 0] = pack_f16x2(v1.x, v0.x);
        Bs[kp][n4 * 4 + 1] = pack_f16x2(v1.y, v0.y);
        Bs[kp][n4 * 4 + 2] = pack_f16x2(v1.z, v0.z);
        Bs[kp][n4 * 4 + 3] = pack_f16x2(v1.w, v0.w);
    }
    __syncthreads();

    // ---- MMA: 8 k-steps, no further syncs ----
    float acc[2][NI][4];
#pragma unroll
    for (int mi = 0; mi < 2; mi++)
#pragma unroll
        for (int ni = 0; ni < NI; ni++)
#pragma unroll
            for (int r = 0; r < 4; r++) acc[mi][ni][r] = 0.0f;

    const int lmRow = lane & 15;
    const int lmKoff = (lane >> 4) * 16;

#pragma unroll
    for (int ks = 0; ks < 8; ks++) {
        uint32_t a[2][4];
#pragma unroll
        for (int mi = 0; mi < 2; mi++) {
            const uint32_t addr = asBase +
                (wr + mi * 16 + lmRow) * AS128 + ks * 32 + lmKoff;
            LDMATRIX_X4(a[mi][0], a[mi][1], a[mi][2], a[mi][3], addr);
        }
#pragma unroll
        for (int ni = 0; ni < NI; ni++) {
            const int col = wc + ni * 8 + g;
            const uint32_t b0 = Bs[ks * 8 + tg][col];
            const uint32_t b1 = Bs[ks * 8 + tg + 4][col];
#pragma unroll
            for (int mi = 0; mi < 2; mi++) {
                MMA_F16(acc[mi][ni], a[mi][0], a[mi][1], a[mi][2], a[mi][3],
                        b0, b1);
            }
        }
    }

    // ---- store C as packed fp16 pairs ----
#pragma unroll
    for (int mi = 0; mi < 2; mi++) {
#pragma unroll
        for (int ni = 0; ni < NI; ni++) {
            const int col = wc + ni * 8 + tg * 2;
            const int r0  = rowBase + wr + mi * 16 + g;
            if (r0 < Nrows) {
                uint32_t pk = pack_f16x2(acc[mi][ni][1], acc[mi][ni][0]);
                *reinterpret_cast<uint32_t*>(C + (size_t)r0 * NC + col) = pk;
            }
            if (r0 + 8 < Nrows) {
                uint32_t pk = pack_f16x2(acc[mi][ni][3], acc[mi][ni][2]);
                *reinterpret_cast<uint32_t*>(C + (size_t)(r0 + 8) * NC + col) = pk;
            }
        }
    }
}

// ================= CSR build ==================================================
__global__ void hist_zero_kernel(int* __restrict__ row_ptr, float* __restrict__ colsum) {
    int i = blockIdx.x * blockDim.x + threadIdx.x;
    if (i <= N_NODES) row_ptr[i] = 0;
    if (i < 3 * F_HID) colsum[i] = 0.0f;
}

__global__ void hist_kernel(const int* __restrict__ row, int* __restrict__ row_ptr) {
    int i = blockIdx.x * blockDim.x + threadIdx.x;
    if (i < N_NNZ) atomicAdd(&row_ptr[row[i] + 1], 1);
}

__global__ __launch_bounds__(SCAN_BS)
void scan_a_kernel(int* __restrict__ data, int* __restrict__ blocksum, int n) {
    __shared__ int sh[SCAN_BS];
    int gid = blockIdx.x * SCAN_BS + threadIdx.x;
    int v = (gid < n) ? data[gid] : 0;
    sh[threadIdx.x] = v;
    __syncthreads();
#pragma unroll
    for (int o = 1; o < SCAN_BS; o <<= 1) {
        int t = (threadIdx.x >= o) ? sh[threadIdx.x - o] : 0;
        __syncthreads();
        sh[threadIdx.x] += t;
        __syncthreads();
    }
    if (gid < n) data[gid] = sh[threadIdx.x];
    if (threadIdx.x == SCAN_BS - 1) blocksum[blockIdx.x] = sh[threadIdx.x];
}

__global__ __launch_bounds__(SCAN_BS)
void scan_b_kernel(int* __restrict__ blocksum, int nb) {
    __shared__ int sh[SCAN_BS];
    int v = (threadIdx.x < nb) ? blocksum[threadIdx.x] : 0;
    sh[threadIdx.x] = v;
    __syncthreads();
#pragma unroll
    for (int o = 1; o < SCAN_BS; o <<= 1) {
        int t = (threadIdx.x >= o) ? sh[threadIdx.x - o] : 0;
        __syncthreads();
        sh[threadIdx.x] += t;
        __syncthreads();
    }
    if (threadIdx.x < nb) blocksum[threadIdx.x] = sh[threadIdx.x];
}

__global__ __launch_bounds__(SCAN_BS)
void scan_c_kernel(int* __restrict__ data, const int* __restrict__ blocksum,
                   int* __restrict__ work, int n) {
    int gid = blockIdx.x * SCAN_BS + threadIdx.x;
    if (gid >= n) return;
    int v = data[gid];
    if (blockIdx.x > 0) v += blocksum[blockIdx.x - 1];
    data[gid] = v;
    work[gid] = v;
}

__global__ void scatter_kernel(const int* __restrict__ row, const int* __restrict__ col,
                               const float* __restrict__ val,
                               int* __restrict__ work,
                               int* __restrict__ csr_col, float* __restrict__ csr_val) {
    int i = blockIdx.x * blockDim.x + threadIdx.x;
    if (i >= N_NNZ) return;
    int pos = atomicAdd(&work[row[i]], 1);
    csr_col[pos] = col[i];
    csr_val[pos] = val[i];
}

// ================= fused CSR aggregation (fp16 gather) =======================
template <int F, int VPL>
__global__ __launch_bounds__(256)
void csr_agg_kernel(const int* __restrict__ row_ptr,
                    const int* __restrict__ csr_col,
                    const float* __restrict__ csr_val,
                    const __half* __restrict__ X,
                    const float* __restrict__ bias,
                    float* __restrict__ Xout,
                    float* __restrict__ colsum) {
    __shared__ float scol[F];
    const int tid  = threadIdx.x;
    const int wid  = tid >> 5;
    const int lane = tid & 31;

    if (tid < F) scol[tid] = 0.0f;
    __syncthreads();

    float bz[VPL];
#pragma unroll
    for (int j = 0; j < VPL; j++) bz[j] = bias[lane * VPL + j];

    float csum[VPL];
#pragma unroll
    for (int j = 0; j < VPL; j++) csum[j] = 0.0f;

    const int rowBase = blockIdx.x * 32 + wid * 4;

#pragma unroll
    for (int rr = 0; rr < 4; rr++) {
        const int r = rowBase + rr;
        const int start = row_ptr[r];
        const int end   = row_ptr[r + 1];

        float acc[VPL];
#pragma unroll
        for (int j = 0; j < VPL; j++) acc[j] = 0.0f;

        for (int base = start; base < end; base += 32) {
            int idx = base + lane;
            int   cv = 0;
            float vv = 0.0f;
            if (idx < end) { cv = csr_col[idx]; vv = csr_val[idx]; }
            int count = min(32, end - base);
            for (int j = 0; j < count; j++) {
                int   c = __shfl_sync(0xffffffffu, cv, j);
                float v = __shfl_sync(0xffffffffu, vv, j);
                if (VPL == 4) {
                    const uint2* xr = reinterpret_cast<const uint2*>(X + (size_t)c * F);
                    uint2 u = xr[lane];
                    float2 f0 = __half22float2(*reinterpret_cast<__half2*>(&u.x));
                    float2 f1 = __half22float2(*reinterpret_cast<__half2*>(&u.y));
                    acc[0] = fmaf(v, f0.x, acc[0]);
                    acc[1] = fmaf(v, f0.y, acc[1]);
                    acc[2] = fmaf(v, f1.x, acc[2]);
                    acc[3] = fmaf(v, f1.y, acc[3]);
                } else {
                    const uint32_t* xr = reinterpret_cast<const uint32_t*>(X + (size_t)c * F);
                    uint32_t u = xr[lane];
                    float2 f0 = __half22float2(*reinterpret_cast<__half2*>(&u));
                    acc[0] = fmaf(v, f0.x, acc[0]);
                    acc[1] = fmaf(v, f0.y, acc[1]);
                }
            }
        }

#pragma unroll
        for (int j = 0; j < VPL; j++) {
            float o = fmaxf(acc[j] + bz[j], 0.0f);
            acc[j] = o;
            csum[j] += o;
        }
        float* od = Xout + (size_t)r * F;
        if (VPL == 4) {
            reinterpret_cast<float4*>(od)[lane] =
                make_float4(acc[0], acc[1], acc[2], acc[3]);
        } else {
            reinterpret_cast<float2*>(od)[lane] = make_float2(acc[0], acc[1]);
        }
    }

#pragma unroll
    for (int j = 0; j < VPL; j++)
        atomicAdd(&scol[lane * VPL + j], csum[j]);
    __syncthreads();
    if (tid < F) atomicAdd(&colsum[tid], scol[tid]);
}

// ---------------- decode with fused final PairNorm ---------------------------
__global__ __launch_bounds__(128)
void decode_kernel(const float* __restrict__ X, const float* __restrict__ colsum,
                   const int* __restrict__ pos, const int* __restrict__ neg,
                   float* __restrict__ out) {
    int warp = (blockIdx.x * blockDim.x + threadIdx.x) >> 5;
    int lane = threadIdx.x & 31;
    if (warp >= N_EDGES) return;
    const int* e = (warp < N_POS) ? (pos + 2 * warp) : (neg + 2 * (warp - N_POS));
    int an = e[0];
    int bn = e[1];
    const float* xa = X + (size_t)an * F_OUT;
    const float* xb = X + (size_t)bn * F_OUT;
    const float m0 = colsum[lane] * INV_N;
    const float m1 = colsum[lane + 32] * INV_N;
    const float a0 = xa[lane] - m0, a1 = xa[lane + 32] - m1;
    const float b0 = xb[lane] - m0, b1 = xb[lane + 32] - m1;
    float saa = a0 * a0 + a1 * a1;
    float sbb = b0 * b0 + b1 * b1;
    float sab = a0 * b0 + a1 * b1;
#pragma unroll
    for (int o = 16; o > 0; o >>= 1) {
        saa += __shfl_xor_sync(0xffffffffu, saa, o);
        sbb += __shfl_xor_sync(0xffffffffu, sbb, o);
        sab += __shfl_xor_sync(0xffffffffu, sab, o);
    }
    if (lane == 0) {
        float s = sab * rsqrtf(1e-6f + saa) * rsqrtf(1e-6f + sbb);
        out[warp] = 1.0f / (1.0f + expf(-s));
    }
}

// ---------------- host orchestration -----------------------------------------
extern "C" void kernel_launch(void* const* d_in, const int* in_sizes, int n_in,
                              void* d_out, int out_size) {
    const float* in_feature = (const float*)d_in[0];
    const int*   adj_row    = (const int*)d_in[1];
    const int*   adj_col    = (const int*)d_in[2];
    const float* adj_val    = (const float*)d_in[3];
    const int*   pos_edge   = (const int*)d_in[4];
    const int*   neg_edge   = (const int*)d_in[5];
    const float* W0 = (const float*)d_in[6];
    const float* b0 = (const float*)d_in[7];
    const float* W1 = (const float*)d_in[8];
    const float* b1 = (const float*)d_in[9];
    const float* W2 = (const float*)d_in[10];
    const float* b2 = (const float*)d_in[11];
    float* out = (float*)d_out;

    __half* support;
    float *x, *colsum, *csr_val;
    int *row_ptr, *row_work, *csr_col, *blocksum;
    cudaGetSymbolAddress((void**)&support,  g_support);
    cudaGetSymbolAddress((void**)&x,        g_x);
    cudaGetSymbolAddress((void**)&colsum,   g_colsum);
    cudaGetSymbolAddress((void**)&row_ptr,  g_row_ptr);
    cudaGetSymbolAddress((void**)&row_work, g_row_work);
    cudaGetSymbolAddress((void**)&csr_col,  g_csr_col);
    cudaGetSymbolAddress((void**)&csr_val,  g_csr_val);
    cudaGetSymbolAddress((void**)&blocksum, g_blocksum);

    // persistent side stream + fork/join events (created once, on the first,
    // non-capturing call; identical work is launched every call)
    static cudaStream_t s_csr = nullptr;
    static cudaEvent_t ev_fork = nullptr, ev_join = nullptr;
    if (s_csr == nullptr) {
        cudaStreamCreateWithFlags(&s_csr, cudaStreamNonBlocking);
        cudaEventCreateWithFlags(&ev_fork, cudaEventDisableTiming);
        cudaEventCreateWithFlags(&ev_join, cudaEventDisableTiming);
    }

    static bool attrDone = false;
    if (!attrDone) {
        cudaFuncSetAttribute(f16_gemm128_kernel<128>,
                             cudaFuncAttributeMaxDynamicSharedMemorySize, 69632);
        cudaFuncSetAttribute(f16_gemm128_kernel<64>,
                             cudaFuncAttributeMaxDynamicSharedMemorySize, 53248);
        attrDone = true;
    }

    const int gBlocks   = (N_NODES + 127) / 128;
    const int aggBlocks = N_NODES / 32;             // 3125

    // ---- fork: CSR build on side stream, concurrent with L0 GEMM ----
    cudaEventRecord(ev_fork, 0);
    cudaStreamWaitEvent(s_csr, ev_fork, 0);
    hist_zero_kernel<<<(N_NODES + 1 + 255) / 256, 256, 0, s_csr>>>(row_ptr, colsum);
    hist_kernel<<<(N_NNZ + 255) / 256, 256, 0, s_csr>>>(adj_row, row_ptr);
    scan_a_kernel<<<SCAN_NB, SCAN_BS, 0, s_csr>>>(row_ptr, blocksum, N_NODES + 1);
    scan_b_kernel<<<1, SCAN_BS, 0, s_csr>>>(blocksum, SCAN_NB);
    scan_c_kernel<<<SCAN_NB, SCAN_BS, 0, s_csr>>>(row_ptr, blocksum, row_work,
                                                  N_NODES + 1);
    scatter_kernel<<<(N_NNZ + 255) / 256, 256, 0, s_csr>>>(adj_row, adj_col,
                                                           adj_val, row_work,
                                                           csr_col, csr_val);
    cudaEventRecord(ev_join, s_csr);

    // ---- layer 0 GEMM on main stream (concurrent with CSR build) ----
    f16_gemm_kernel<<<gBlocks, 256>>>(in_feature, W0, support, N_NODES, F_IN);

    // join before aggregation needs CSR + zeroed colsum
    cudaStreamWaitEvent(0, ev_join, 0);

    // ---- layer 0 aggregation ----
    csr_agg_kernel<128, 4><<<aggBlocks, 256>>>(row_ptr, csr_col, csr_val,
                                               support, b0, x, colsum + 0 * F_HID);

    // ---- layer 1 (PairNorm folded into GEMM, single-load) ----
    f16_gemm128_kernel<128><<<gBlocks, 256, 69632>>>(x, W1, support, N_NODES,
                                                     colsum + 0 * F_HID);
    csr_agg_kernel<128, 4><<<aggBlocks, 256>>>(row_ptr, csr_col, csr_val,
                                               support, b1, x, colsum + 1 * F_HID);

    // ---- layer 2 ----
    f16_gemm128_kernel<64><<<gBlocks, 256, 53248>>>(x, W2, support, N_NODES,
                                                    colsum + 1 * F_HID);
    csr_agg_kernel<64, 2><<<aggBlocks, 256>>>(row_ptr, csr_col, csr_val,
                                              support, b2, x, colsum + 2 * F_HID);

    // ---- decode with fused final pairnorm ----
    decode_kernel<<<(N_EDGES * 32 + 127) / 128, 128>>>(x, colsum + 2 * F_HID,
                                                       pos_edge, neg_edge, out);
}